// round 1
// baseline (speedup 1.0000x reference)
#include <cuda_runtime.h>
#include <math.h>

#define B_ROWS 16384
#define IN1    256
#define HD     512
#define NB     16
#define NPART  128   // partial-sum blocks for stats

typedef unsigned long long u64;

// ---------------- scratch (device globals: no allocations allowed) ----------
__device__ float  g_mu1[IN1], g_inv1[IN1];
__device__ float  g_mu2[HD],  g_inv2[HD];
__device__ float  g_mu3[HD],  g_inv3[HD];
__device__ float  g_ps[NPART * HD];
__device__ float  g_pq[NPART * HD];
__device__ float2 g_tr1[B_ROWS * IN1];          // (t, r) for layer 1 input
__device__ float2 g_tr2[B_ROWS * HD];           // (t, r) for layer 2 / reused for layer 3
__device__ float  g_h1[B_ROWS * HD];
__device__ float  g_h2[B_ROWS * HD];
__device__ float  g_cp1[IN1 * NB * HD];         // transformed coeffs, layout [i][j][O]
__device__ float  g_cp2[HD * NB * HD];
__device__ float  g_cp3[HD * NB];

// ---------------- packed f32x2 helpers --------------------------------------
__device__ __forceinline__ u64 pk2(float lo, float hi) {
    u64 d; asm("mov.b64 %0, {%1, %2};" : "=l"(d) : "f"(lo), "f"(hi)); return d;
}
__device__ __forceinline__ void upk2(u64 v, float &lo, float &hi) {
    asm("mov.b64 {%0, %1}, %2;" : "=f"(lo), "=f"(hi) : "l"(v));
}
__device__ __forceinline__ u64 ffma2(u64 a, u64 b, u64 c) {
    u64 d; asm("fma.rn.f32x2 %0, %1, %2, %3;" : "=l"(d) : "l"(a), "l"(b), "l"(c));
    return d;
}

// ---------------- stats: per-column mean / unbiased std ---------------------
// Pass 1: each of NPART blocks reduces B_ROWS/NPART rows (deterministic).
__global__ void k_stats_part(const float* __restrict__ src, int C) {
    const int rows = B_ROWS / NPART;
    const int r0 = blockIdx.x * rows;
    float s[2] = {0.f, 0.f}, q[2] = {0.f, 0.f};
    const int ncc = C >> 8;   // C is 256 or 512, blockDim = 256
    for (int rr = 0; rr < rows; rr++) {
        const float* row = src + (size_t)(r0 + rr) * C;
        for (int cc = 0; cc < ncc; cc++) {
            float v = row[threadIdx.x + (cc << 8)];
            s[cc] += v;
            q[cc] = fmaf(v, v, q[cc]);
        }
    }
    for (int cc = 0; cc < ncc; cc++) {
        g_ps[blockIdx.x * C + threadIdx.x + (cc << 8)] = s[cc];
        g_pq[blockIdx.x * C + threadIdx.x + (cc << 8)] = q[cc];
    }
}

// Pass 2: finalize mu and 1/(sd+1e-6)
__global__ void k_stats_fin(int C, float* __restrict__ mu, float* __restrict__ inv) {
    int c = blockIdx.x * blockDim.x + threadIdx.x;
    if (c >= C) return;
    float s = 0.f, q = 0.f;
    for (int k = 0; k < NPART; k++) { s += g_ps[k * C + c]; q += g_pq[k * C + c]; }
    float m = s / (float)B_ROWS;
    float var = (q - s * m) / (float)(B_ROWS - 1);
    float sd = sqrtf(fmaxf(var, 0.f));
    mu[c] = m;
    inv[c] = 1.f / (sd + 1e-6f);
}

// ---------------- (t, r) precompute ------------------------------------------
// xn = clip((v-mu)*inv, -3, 3); t = exp(-2xn^2-8xn); r = exp(16xn/15)
__global__ void k_prep_tr(const float* __restrict__ src,
                          const float* __restrict__ mu,
                          const float* __restrict__ inv,
                          int cmask, int total, float2* __restrict__ dst) {
    for (int idx = blockIdx.x * blockDim.x + threadIdx.x; idx < total;
         idx += gridDim.x * blockDim.x) {
        int c = idx & cmask;
        float xn = (src[idx] - mu[c]) * inv[c];
        xn = fminf(3.f, fmaxf(-3.f, xn));
        float t = __expf(fmaf(-2.f * xn, xn, -8.f * xn));
        float r = __expf(xn * (16.f / 15.f));
        dst[idx] = make_float2(t, r);
    }
}

// ---------------- coefficient transform --------------------------------------
// dst[(i*16+j)*O + o] = src[(o*IN+i)*16 + n] * Kn, with n = 15-j (Horner order)
__global__ void k_prep_coeffs(const float* __restrict__ src, int O, int IN_,
                              float* __restrict__ dst) {
    int i = blockIdx.x;
    for (int w = threadIdx.x; w < NB * O; w += blockDim.x) {
        int o = w % O;
        int j = w / O;
        int n = 15 - j;
        float cn = fmaf((float)n, 4.f / 15.f, -2.f);
        float K = expf(-2.f * cn * cn);
        dst[(size_t)(i * NB + j) * O + o] = src[((size_t)o * IN_ + i) * NB + n] * K;
    }
}

// ---------------- main Horner-GEMM layer -------------------------------------
// out[b,o] = (tanh of) sum_i t[b,i] * P_{o,i}(r[b,i]),  P = 15-step Horner
// Tiles: BM=64 rows, BN=64 cols, BI=8 inputs/step. 128 threads, 4x8 per thread.
template <bool TANH>
__global__ void __launch_bounds__(128)
k_layer(const float2* __restrict__ tr, const float* __restrict__ cp,
        float* __restrict__ out, int IN_, int O) {
    __shared__ float2 s_tr[8][64];
    __shared__ __align__(16) float s_cp[8][16][64];

    const int tid = threadIdx.x;
    const int tx = tid & 15;      // row group (4 rows each)
    const int ty = tid >> 4;      // col group (8 cols each)
    const int bm0 = blockIdx.y * 64;
    const int on0 = blockIdx.x * 64;

    u64 acc[4][4];
#pragma unroll
    for (int mm = 0; mm < 4; mm++)
#pragma unroll
        for (int g = 0; g < 4; g++) acc[mm][g] = 0ull;

    for (int i0 = 0; i0 < IN_; i0 += 8) {
        // load (t,r) tile: 512 float2
#pragma unroll
        for (int k = 0; k < 4; k++) {
            int e = tid + 128 * k;
            int il = e & 7, m = e >> 3;
            s_tr[il][m] = tr[(size_t)(bm0 + m) * IN_ + i0 + il];
        }
        // load coeff tile: [8][16][64] floats as float4
#pragma unroll
        for (int k = 0; k < 16; k++) {
            int f = tid + 128 * k;
            int il = f >> 8, rest = f & 255;
            int j = rest >> 4, g4 = rest & 15;
            const float4* s =
                reinterpret_cast<const float4*>(cp + (size_t)((i0 + il) * NB + j) * O + on0);
            reinterpret_cast<float4*>(&s_cp[il][j][0])[g4] = s[g4];
        }
        __syncthreads();

#pragma unroll
        for (int il = 0; il < 8; il++) {
            u64 t2[4], r2[4];
#pragma unroll
            for (int mm = 0; mm < 4; mm++) {
                float2 v = s_tr[il][tx * 4 + mm];
                t2[mm] = pk2(v.x, v.x);
                r2[mm] = pk2(v.y, v.y);
            }
            u64 p[4][4];
            {
                float4 c0 = *reinterpret_cast<const float4*>(&s_cp[il][0][ty * 8]);
                float4 c1 = *reinterpret_cast<const float4*>(&s_cp[il][0][ty * 8 + 4]);
                u64 cA = pk2(c0.x, c0.y), cB = pk2(c0.z, c0.w);
                u64 cC = pk2(c1.x, c1.y), cD = pk2(c1.z, c1.w);
#pragma unroll
                for (int mm = 0; mm < 4; mm++) {
                    p[mm][0] = cA; p[mm][1] = cB; p[mm][2] = cC; p[mm][3] = cD;
                }
            }
#pragma unroll
            for (int j = 1; j < 16; j++) {
                float4 c0 = *reinterpret_cast<const float4*>(&s_cp[il][j][ty * 8]);
                float4 c1 = *reinterpret_cast<const float4*>(&s_cp[il][j][ty * 8 + 4]);
                u64 cc[4] = {pk2(c0.x, c0.y), pk2(c0.z, c0.w),
                             pk2(c1.x, c1.y), pk2(c1.z, c1.w)};
#pragma unroll
                for (int mm = 0; mm < 4; mm++)
#pragma unroll
                    for (int g = 0; g < 4; g++)
                        p[mm][g] = ffma2(p[mm][g], r2[mm], cc[g]);
            }
#pragma unroll
            for (int mm = 0; mm < 4; mm++)
#pragma unroll
                for (int g = 0; g < 4; g++)
                    acc[mm][g] = ffma2(t2[mm], p[mm][g], acc[mm][g]);
        }
        __syncthreads();
    }

#pragma unroll
    for (int mm = 0; mm < 4; mm++) {
        int row = bm0 + tx * 4 + mm;
        float v[8];
#pragma unroll
        for (int g = 0; g < 4; g++) upk2(acc[mm][g], v[2 * g], v[2 * g + 1]);
        if (TANH) {
#pragma unroll
            for (int k = 0; k < 8; k++) v[k] = tanhf(v[k]);
        }
        float4 w0 = make_float4(v[0], v[1], v[2], v[3]);
        float4 w1 = make_float4(v[4], v[5], v[6], v[7]);
        float4* dst = reinterpret_cast<float4*>(out + (size_t)row * O + on0 + ty * 8);
        dst[0] = w0;
        dst[1] = w1;
    }
}

// ---------------- layer 3 (O=1) + skip ---------------------------------------
__global__ void k_final(const float2* __restrict__ tr, const float* __restrict__ cp3,
                        const float* __restrict__ x, const float* __restrict__ sw,
                        const float* __restrict__ sb, float* __restrict__ out) {
    int warp = threadIdx.x >> 5, lane = threadIdx.x & 31;
    int b = blockIdx.x * 8 + warp;
    float acc = 0.f;
    for (int i = lane; i < HD; i += 32) {
        float2 v = tr[(size_t)b * HD + i];
        const float* c = &cp3[i * NB];
        float p = c[0];
#pragma unroll
        for (int j = 1; j < NB; j++) p = fmaf(p, v.y, c[j]);
        acc = fmaf(v.x, p, acc);
    }
    for (int cidx = lane; cidx < IN1; cidx += 32)
        acc = fmaf(x[(size_t)b * IN1 + cidx], sw[cidx], acc);
#pragma unroll
    for (int off = 16; off; off >>= 1) acc += __shfl_xor_sync(0xffffffffu, acc, off);
    if (lane == 0) out[b] = acc + sb[0];
}

// ---------------- launch -----------------------------------------------------
extern "C" void kernel_launch(void* const* d_in, const int* in_sizes, int n_in,
                              void* d_out, int out_size) {
    const float* x  = (const float*)d_in[0];
    const float* c1 = (const float*)d_in[1];
    const float* c2 = (const float*)d_in[2];
    const float* c3 = (const float*)d_in[3];
    const float* sw = (const float*)d_in[4];
    const float* sb = (const float*)d_in[5];
    float* out = (float*)d_out;

    float2 *tr1, *tr2;
    float *h1, *h2, *cp1, *cp2, *cp3;
    float *mu1, *inv1, *mu2, *inv2, *mu3, *inv3;
    cudaGetSymbolAddress((void**)&tr1,  g_tr1);
    cudaGetSymbolAddress((void**)&tr2,  g_tr2);
    cudaGetSymbolAddress((void**)&h1,   g_h1);
    cudaGetSymbolAddress((void**)&h2,   g_h2);
    cudaGetSymbolAddress((void**)&cp1,  g_cp1);
    cudaGetSymbolAddress((void**)&cp2,  g_cp2);
    cudaGetSymbolAddress((void**)&cp3,  g_cp3);
    cudaGetSymbolAddress((void**)&mu1,  g_mu1);
    cudaGetSymbolAddress((void**)&inv1, g_inv1);
    cudaGetSymbolAddress((void**)&mu2,  g_mu2);
    cudaGetSymbolAddress((void**)&inv2, g_inv2);
    cudaGetSymbolAddress((void**)&mu3,  g_mu3);
    cudaGetSymbolAddress((void**)&inv3, g_inv3);

    // coefficient transforms (cheap, every call: deterministic)
    k_prep_coeffs<<<IN1, 256>>>(c1, HD, IN1, cp1);
    k_prep_coeffs<<<HD,  256>>>(c2, HD, HD,  cp2);
    k_prep_coeffs<<<HD,  256>>>(c3, 1,  HD,  cp3);

    // layer 1
    k_stats_part<<<NPART, 256>>>(x, IN1);
    k_stats_fin<<<1, 256>>>(IN1, mu1, inv1);
    k_prep_tr<<<2048, 256>>>(x, mu1, inv1, IN1 - 1, B_ROWS * IN1, tr1);
    k_layer<true><<<dim3(HD / 64, B_ROWS / 64), 128>>>(tr1, cp1, h1, IN1, HD);

    // layer 2
    k_stats_part<<<NPART, 256>>>(h1, HD);
    k_stats_fin<<<2, 256>>>(HD, mu2, inv2);
    k_prep_tr<<<4096, 256>>>(h1, mu2, inv2, HD - 1, B_ROWS * HD, tr2);
    k_layer<true><<<dim3(HD / 64, B_ROWS / 64), 128>>>(tr2, cp2, h2, HD, HD);

    // layer 3 + skip
    k_stats_part<<<NPART, 256>>>(h2, HD);
    k_stats_fin<<<2, 256>>>(HD, mu3, inv3);
    k_prep_tr<<<4096, 256>>>(h2, mu3, inv3, HD - 1, B_ROWS * HD, tr2);  // reuse tr2
    k_final<<<B_ROWS / 8, 256>>>(tr2, cp3, x, sw, sb, out);
}